// round 13
// baseline (speedup 1.0000x reference)
#include <cuda_runtime.h>

#define H 512
#define W 512
#define NB 32

#define SQRT_APPROX(d, a) \
    asm("sqrt.approx.f32 %0, %1;" : "=f"(d) : "f"(a))

// Persistent grid-stride version of the R6 champion.
// Tile = 2 full rows handled by a 256-thread CTA (thread = 4 px, shuffle halo,
// approx sqrt, streaming stores). 1184 resident CTAs loop over the 8192 tiles,
// letting the next tile's independent loads overlap the current tile's
// compute/store tail (cross-iteration MLP) and removing wave quantization.
__global__ __launch_bounds__(256) void sqdiff_mag_kernel(
    const float* __restrict__ x, float* __restrict__ out)
{
    const int lane = threadIdx.x & 31;
    const int wg   = threadIdx.x & 127;           // float4 group in row
    const int sub  = threadIdx.x >> 7;            // 0/1: which row of the tile
    const int w    = wg << 2;
    const int wbase = w & ~127;                   // warp's 128-px strip

    const size_t plane = (size_t)H * W;
    const int NT = NB * (H / 2);                  // 8192 tiles

    for (int t = blockIdx.x; t < NT; t += gridDim.x) {
        int n = t >> 8;                           // tile / 256
        int h = ((t & 255) << 1) + sub;

        const float* g = x + ((size_t)n * 3 + 1) * plane;  // channel 1

        float rm[6], rc[6], rp[6];

        #define LOAD_ROW(dst, hh)                                              \
        {                                                                      \
            const float* p = g + (size_t)(hh) * W + w;                         \
            float4 v = *reinterpret_cast<const float4*>(p);                    \
            dst[1] = v.x; dst[2] = v.y; dst[3] = v.z; dst[4] = v.w;            \
            float lft = __shfl_up_sync(0xffffffffu, v.w, 1);                   \
            float rgt = __shfl_down_sync(0xffffffffu, v.x, 1);                 \
            if (lane == 0)  lft = (wbase > 0)       ? __ldg(p - 1) : 0.0f;     \
            if (lane == 31) rgt = (wbase + 128 < W) ? __ldg(p + 4) : 0.0f;     \
            dst[0] = lft; dst[5] = rgt;                                        \
        }

        LOAD_ROW(rc, h)
        if (h > 0) {
            LOAD_ROW(rm, h - 1)
        } else {
            #pragma unroll
            for (int i = 0; i < 6; i++) rm[i] = 0.0f;
        }
        if (h + 1 < H) {
            LOAD_ROW(rp, h + 1)
        } else {
            #pragma unroll
            for (int i = 0; i < 6; i++) rp[i] = 0.0f;
        }
        #undef LOAD_ROW

        float4 res;
        float* resp = reinterpret_cast<float*>(&res);

        #pragma unroll
        for (int i = 0; i < 4; i++) {
            float c  = rc[i + 1];
            float d0 = c - rc[i + 2];
            float d1 = c - rc[i];
            float d2 = c - rp[i + 1];
            float d3 = c - rm[i + 1];
            float d4 = c - rp[i + 2];
            float d5 = c - rp[i];
            float d6 = c - rm[i + 2];
            float d7 = c - rm[i];
            float s = d0 * d0;
            s = fmaf(d1, d1, s);
            s = fmaf(d2, d2, s);
            s = fmaf(d3, d3, s);
            s = fmaf(d4, d4, s);
            s = fmaf(d5, d5, s);
            s = fmaf(d6, d6, s);
            s = fmaf(d7, d7, s);
            SQRT_APPROX(resp[i], s);
        }

        float* ob = out + (size_t)n * 3 * plane + (size_t)h * W + w;
        __stcs(reinterpret_cast<float4*>(ob),             res);
        __stcs(reinterpret_cast<float4*>(ob + plane),     res);
        __stcs(reinterpret_cast<float4*>(ob + 2 * plane), res);
    }
}

extern "C" void kernel_launch(void* const* d_in, const int* in_sizes, int n_in,
                              void* d_out, int out_size)
{
    const float* x = (const float*)d_in[0];
    float* out = (float*)d_out;

    // One resident wave: 8 CTAs/SM (32 regs x 256 thr) x 148 SMs.
    sqdiff_mag_kernel<<<1184, 256>>>(x, out);
}

// round 15
// speedup vs baseline: 1.1905x; 1.1905x over previous
#include <cuda_runtime.h>
#include <cstdint>

#define H 512
#define W 512
#define NB 32

#define SQRT_APPROX(d, a) \
    asm("sqrt.approx.f32 %0, %1;" : "=f"(d) : "f"(a))

// Per-access L2 policy: evict_last for the input (keep resident) while the
// output streams out via evict-first __stcs. 16B loads need the
// createpolicy + L2::cache_hint form (direct .L2::evict_last needs 32B).
#define LDG4_EL(v, p, pol)                                                     \
    asm("ld.global.nc.L2::cache_hint.v4.f32 {%0,%1,%2,%3}, [%4], %5;"          \
        : "=f"((v).x), "=f"((v).y), "=f"((v).z), "=f"((v).w)                   \
        : "l"(p), "l"(pol))

// R6 champion shape: block = 256 threads = 2 full rows; thread = 4 px of one
// row; shuffle halo; approx sqrt; streaming stores. grid = (H/2, NB).
__global__ __launch_bounds__(256) void sqdiff_mag_kernel(
    const float* __restrict__ x, float* __restrict__ out)
{
    uint64_t pol;
    asm("createpolicy.fractional.L2::evict_last.b64 %0, 1.0;" : "=l"(pol));

    int lane = threadIdx.x & 31;
    int wg   = threadIdx.x & 127;                     // float4 group in row
    int h    = (blockIdx.x << 1) + (threadIdx.x >> 7);
    int n    = blockIdx.y;

    int w     = wg << 2;
    int wbase = w & ~127;                             // warp's 128-px strip

    const size_t plane = (size_t)H * W;
    const float* g = x + ((size_t)n * 3 + 1) * plane; // channel 1

    float rm[6], rc[6], rp[6];

    #define LOAD_ROW(dst, hh)                                                  \
    {                                                                          \
        const float* p = g + (size_t)(hh) * W + w;                             \
        float4 v;                                                              \
        LDG4_EL(v, p, pol);                                                    \
        dst[1] = v.x; dst[2] = v.y; dst[3] = v.z; dst[4] = v.w;                \
        float lft = __shfl_up_sync(0xffffffffu, v.w, 1);                       \
        float rgt = __shfl_down_sync(0xffffffffu, v.x, 1);                     \
        if (lane == 0)  lft = (wbase > 0)       ? __ldg(p - 1) : 0.0f;         \
        if (lane == 31) rgt = (wbase + 128 < W) ? __ldg(p + 4) : 0.0f;         \
        dst[0] = lft; dst[5] = rgt;                                            \
    }

    LOAD_ROW(rc, h)
    if (h > 0) {
        LOAD_ROW(rm, h - 1)
    } else {
        #pragma unroll
        for (int i = 0; i < 6; i++) rm[i] = 0.0f;
    }
    if (h + 1 < H) {
        LOAD_ROW(rp, h + 1)
    } else {
        #pragma unroll
        for (int i = 0; i < 6; i++) rp[i] = 0.0f;
    }
    #undef LOAD_ROW

    float4 res;
    float* resp = reinterpret_cast<float*>(&res);

    #pragma unroll
    for (int i = 0; i < 4; i++) {
        float c  = rc[i + 1];
        float d0 = c - rc[i + 2];
        float d1 = c - rc[i];
        float d2 = c - rp[i + 1];
        float d3 = c - rm[i + 1];
        float d4 = c - rp[i + 2];
        float d5 = c - rp[i];
        float d6 = c - rm[i + 2];
        float d7 = c - rm[i];
        float s = d0 * d0;
        s = fmaf(d1, d1, s);
        s = fmaf(d2, d2, s);
        s = fmaf(d3, d3, s);
        s = fmaf(d4, d4, s);
        s = fmaf(d5, d5, s);
        s = fmaf(d6, d6, s);
        s = fmaf(d7, d7, s);
        SQRT_APPROX(resp[i], s);
    }

    float* ob = out + (size_t)n * 3 * plane + (size_t)h * W + w;
    __stcs(reinterpret_cast<float4*>(ob),             res);
    __stcs(reinterpret_cast<float4*>(ob + plane),     res);
    __stcs(reinterpret_cast<float4*>(ob + 2 * plane), res);
}

extern "C" void kernel_launch(void* const* d_in, const int* in_sizes, int n_in,
                              void* d_out, int out_size)
{
    const float* x = (const float*)d_in[0];
    float* out = (float*)d_out;

    dim3 grid(H / 2, NB);     // 256 x 32 blocks of 256 threads
    sqdiff_mag_kernel<<<grid, 256>>>(x, out);
}